// round 9
// baseline (speedup 1.0000x reference)
#include <cuda_runtime.h>

#define NB 64
#define NP 1024
#define M1 128
#define M2 32

typedef unsigned long long ull;

#define PACKF2(d, lo, hi) asm("mov.b64 %0, {%1, %2};" : "=l"(d) : "f"(lo), "f"(hi))
#define UNPACKF2(lo, hi, d) asm("mov.b64 {%0, %1}, %2;" : "=f"(lo), "=f"(hi) : "l"(d))
#define FFMA2(acc, w, x) asm("fma.rn.f32x2 %0, %1, %2, %0;" : "+l"(acc) : "l"(w), "l"(x))

__device__ float g_bufA[(size_t)NB * 128 * M1 * 64];
__device__ float g_bufB[(size_t)NB * 128 * M1 * 64];
__device__ float g_f1[NB * 128 * M1];
__device__ float g_c1[NB * M1 * 3];
__device__ float g_c2[NB * M2 * 3];
__device__ int   g_i1[NB * M1];
__device__ int   g_i2[NB * M2];
__device__ int   g_n1[NB * M1 * 64];
__device__ int   g_n2[NB * M2 * 64];
__device__ float g_x3[NB * 259 * M2];
__device__ float g_z3a[NB * 512 * M2];
__device__ float g_z3b[NB * 256 * M2];
__device__ float g_xc[515 * NB];
__device__ float g_fa1[512 * NB];
__device__ float g_fa2[256 * NB];
__device__ __align__(16) float g_wt[350000];
__device__ float g_sum[512], g_sq[512];
__device__ float g_meanL[9][512], g_rstdL[9][512];
__device__ int   g_cnt;

__device__ __forceinline__ void finalize_block(int Cout, float invN, int slot,
                                               int gridTotal, int tid, int bdim) {
    __shared__ int s_last;
    __threadfence();
    __syncthreads();
    if (tid == 0) s_last = (atomicAdd(&g_cnt, 1) == gridTotal - 1) ? 1 : 0;
    __syncthreads();
    if (s_last) {
        for (int c = tid; c < Cout; c += bdim) {
            float s = __ldcg(&g_sum[c]), q = __ldcg(&g_sq[c]);
            float mn = s * invN;
            g_meanL[slot][c] = mn;
            g_rstdL[slot][c] = rsqrtf(q * invN - mn * mn + 1e-5f);
            g_sum[c] = 0.0f; g_sq[c] = 0.0f;
        }
        if (tid == 0) g_cnt = 0;
    }
}

__global__ void tw_all(const float* w1a, const float* w1b, const float* w1c,
                       const float* w2a, const float* w2b, const float* w2c,
                       const float* w3a, const float* w3b, const float* w3c) {
    const float* src[9] = { w1a, w1b, w1c, w2a, w2b, w2c, w3a, w3b, w3c };
    const int  O[9] = { 64, 64, 128, 128, 128, 256, 256, 256, 512 };
    const int  C[9] = { 3, 64, 64, 131, 128, 128, 259, 256, 256 };
    const int off[9] = { 0, 192, 4288, 12480, 29248, 45632, 78400, 144704, 210240 };
    int stride = gridDim.x * blockDim.x;
    int t0 = blockIdx.x * blockDim.x + threadIdx.x;
    for (int s = 0; s < 9; s++) {
        const float* W = src[s]; float* Wt = g_wt + off[s];
        int n = O[s] * C[s], Cs = C[s], Os = O[s];
        for (int i = t0; i < n; i += stride) {
            int o = i / Cs, c = i - o * Cs;
            Wt[c * Os + o] = W[i];
        }
    }
}

// ---- fused FPS(128) + ball-query for stage 1 ----
__global__ __launch_bounds__(1024) void fpsbq1_k(const float* __restrict__ coords) {
    __shared__ float sp[3 * NP];
    __shared__ float sv[32]; __shared__ int si[32];
    __shared__ float sc[3]; __shared__ int sfar;
    int b = blockIdx.x, t = threadIdx.x, lane = t & 31, w = t >> 5;
    const float* cb = coords + (size_t)b * 3 * NP;
    for (int i = t; i < 3 * NP; i += 1024) sp[i] = cb[i];
    __syncthreads();
    float px = sp[t], py = sp[NP + t], pz = sp[2 * NP + t];
    float dist = 1e10f; int far = 0;
    for (int s = 0; s < 128; s++) {
        if (t == far) {
            sc[0] = px; sc[1] = py; sc[2] = pz;
            g_i1[b * 128 + s] = far;
            float* cw = g_c1 + ((size_t)b * 128 + s) * 3;
            cw[0] = px; cw[1] = py; cw[2] = pz;
        }
        __syncthreads();
        float dx = __fadd_rn(px, -sc[0]), dy = __fadd_rn(py, -sc[1]), dz = __fadd_rn(pz, -sc[2]);
        float d = __fadd_rn(__fadd_rn(__fmul_rn(dx, dx), __fmul_rn(dy, dy)), __fmul_rn(dz, dz));
        dist = fminf(dist, d);
        float v = dist; int ii = t;
        #pragma unroll
        for (int o = 16; o; o >>= 1) {
            float ov = __shfl_down_sync(0xffffffffu, v, o);
            int oi = __shfl_down_sync(0xffffffffu, ii, o);
            if (ov > v || (ov == v && oi < ii)) { v = ov; ii = oi; }
        }
        if (lane == 0) { sv[w] = v; si[w] = ii; }
        __syncthreads();
        if (t < 32) {
            float v2 = sv[t]; int i2 = si[t];
            #pragma unroll
            for (int o = 16; o; o >>= 1) {
                float ov = __shfl_down_sync(0xffffffffu, v2, o);
                int oi = __shfl_down_sync(0xffffffffu, i2, o);
                if (ov > v2 || (ov == v2 && oi < i2)) { v2 = ov; i2 = oi; }
            }
            if (t == 0) sfar = i2;
        }
        __syncthreads();
        far = sfar;
    }
    __syncthreads();
    float r2 = (float)(0.2 * 0.2);
    for (int mi = 0; mi < 4; mi++) {
        int m = w * 4 + mi;
        const float* cr = g_c1 + ((size_t)b * 128 + m) * 3;
        float cx = cr[0], cy = cr[1], cz = cr[2];
        int base = (b * 128 + m) * 64, cnt = 0, firstj = -1;
        for (int ch = 0; ch < 32; ch++) {
            int j = (ch << 5) + lane;
            float dx = __fadd_rn(cx, -sp[j]);
            float dy = __fadd_rn(cy, -sp[NP + j]);
            float dz = __fadd_rn(cz, -sp[2 * NP + j]);
            float d = __fadd_rn(__fadd_rn(__fmul_rn(dx, dx), __fmul_rn(dy, dy)), __fmul_rn(dz, dz));
            bool hit = d < r2;
            unsigned mask = __ballot_sync(0xffffffffu, hit);
            int pos = cnt + __popc(mask & ((1u << lane) - 1u));
            if (hit && pos < 64) g_n1[base + pos] = j;
            if (firstj < 0 && mask) firstj = (ch << 5) + __ffs(mask) - 1;
            cnt += __popc(mask);
            if (cnt >= 64) break;
        }
        for (int s2 = cnt + lane; s2 < 64; s2 += 32) g_n1[base + s2] = firstj;
    }
}

// ---- fused FPS(32) + ball-query for stage 2 ----
__global__ __launch_bounds__(128) void fpsbq2_k() {
    __shared__ float sp[3 * 128];
    __shared__ float sv[4]; __shared__ int si[4];
    __shared__ float sc[3]; __shared__ int sfar;
    int b = blockIdx.x, t = threadIdx.x, lane = t & 31, w = t >> 5;
    for (int i = t; i < 384; i += 128) {
        int c = i >> 7, j = i & 127;
        sp[i] = g_c1[((size_t)b * 128 + j) * 3 + c];
    }
    __syncthreads();
    float px = sp[t], py = sp[128 + t], pz = sp[256 + t];
    float dist = 1e10f; int far = 0;
    for (int s = 0; s < 32; s++) {
        if (t == far) {
            sc[0] = px; sc[1] = py; sc[2] = pz;
            g_i2[b * 32 + s] = far;
            float* cw = g_c2 + ((size_t)b * 32 + s) * 3;
            cw[0] = px; cw[1] = py; cw[2] = pz;
        }
        __syncthreads();
        float dx = __fadd_rn(px, -sc[0]), dy = __fadd_rn(py, -sc[1]), dz = __fadd_rn(pz, -sc[2]);
        float d = __fadd_rn(__fadd_rn(__fmul_rn(dx, dx), __fmul_rn(dy, dy)), __fmul_rn(dz, dz));
        dist = fminf(dist, d);
        float v = dist; int ii = t;
        #pragma unroll
        for (int o = 16; o; o >>= 1) {
            float ov = __shfl_down_sync(0xffffffffu, v, o);
            int oi = __shfl_down_sync(0xffffffffu, ii, o);
            if (ov > v || (ov == v && oi < ii)) { v = ov; ii = oi; }
        }
        if (lane == 0) { sv[w] = v; si[w] = ii; }
        __syncthreads();
        if (t < 32) {
            float v2 = (t < 4) ? sv[t] : -1.0f;
            int i2 = (t < 4) ? si[t] : 0x7fffffff;
            #pragma unroll
            for (int o = 16; o; o >>= 1) {
                float ov = __shfl_down_sync(0xffffffffu, v2, o);
                int oi = __shfl_down_sync(0xffffffffu, i2, o);
                if (ov > v2 || (ov == v2 && oi < i2)) { v2 = ov; i2 = oi; }
            }
            if (t == 0) sfar = i2;
        }
        __syncthreads();
        far = sfar;
    }
    __syncthreads();
    float r2 = (float)(0.4 * 0.4);
    for (int mi = 0; mi < 8; mi++) {
        int m = w * 8 + mi;
        const float* cr = g_c2 + ((size_t)b * 32 + m) * 3;
        float cx = cr[0], cy = cr[1], cz = cr[2];
        int base = (b * 32 + m) * 64, cnt = 0, firstj = -1;
        for (int ch = 0; ch < 4; ch++) {
            int j = (ch << 5) + lane;
            float dx = __fadd_rn(cx, -sp[j]);
            float dy = __fadd_rn(cy, -sp[128 + j]);
            float dz = __fadd_rn(cz, -sp[256 + j]);
            float d = __fadd_rn(__fadd_rn(__fmul_rn(dx, dx), __fmul_rn(dy, dy)), __fmul_rn(dz, dz));
            bool hit = d < r2;
            unsigned mask = __ballot_sync(0xffffffffu, hit);
            int pos = cnt + __popc(mask & ((1u << lane) - 1u));
            if (hit && pos < 64) g_n2[base + pos] = j;
            if (firstj < 0 && mask) firstj = (ch << 5) + __ffs(mask) - 1;
            cnt += __popc(mask);
            if (cnt >= 64) break;
        }
        for (int s2 = cnt + lane; s2 < 64; s2 += 32) g_n2[base + s2] = firstj;
    }
}

// ---- stage-1 layer-1: fused gather + 3->64 conv, smem stats, finalize slot0 ----
__global__ __launch_bounds__(256) void convA_k(const float* __restrict__ coords,
                                               const float* __restrict__ w1a) {
    __shared__ float s_in[3 * 64];
    __shared__ float sW[3][64];
    __shared__ int sn[64];
    __shared__ float scx[3];
    __shared__ float sS[64], sQ[64];
    int bm = blockIdx.x, b = bm >> 7, m = bm & 127;
    int tid = threadIdx.x, lane = tid & 31, wp = tid >> 5;
    if (tid < 64) { sn[tid] = g_n1[bm * 64 + tid]; sS[tid] = 0.0f; sQ[tid] = 0.0f; }
    if (tid >= 64 && tid < 67) scx[tid - 64] = g_c1[((size_t)b * M1 + m) * 3 + (tid - 64)];
    if (tid >= 64 && tid < 256) {
        int i = tid - 64;
        if (i < 192) { int o = i / 3, c = i - o * 3; sW[c][o] = w1a[i]; }
    }
    __syncthreads();
    if (tid < 192) {
        int c = tid >> 6, k = tid & 63;
        s_in[c * 64 + k] = coords[(size_t)b * 3 * NP + c * NP + sn[k]] - scx[c];
    }
    __syncthreads();
    int ob = wp * 8;
    float a[8][2];
    #pragma unroll
    for (int j = 0; j < 8; j++) { a[j][0] = 0.0f; a[j][1] = 0.0f; }
    const float2* xrow = (const float2*)s_in + lane;
    #pragma unroll
    for (int c = 0; c < 3; c++) {
        float2 xv = xrow[c * 32];
        float4 w0 = *(const float4*)&sW[c][ob];
        float4 w1 = *(const float4*)&sW[c][ob + 4];
        float wv[8] = { w0.x, w0.y, w0.z, w0.w, w1.x, w1.y, w1.z, w1.w };
        #pragma unroll
        for (int j = 0; j < 8; j++) { a[j][0] += wv[j] * xv.x; a[j][1] += wv[j] * xv.y; }
    }
    size_t MK = (size_t)M1 * 64;
    float* outb = g_bufA + (size_t)b * 64 * MK + (size_t)m * 64;
    float ss[8], qq[8];
    #pragma unroll
    for (int j = 0; j < 8; j++) {
        *(float2*)(outb + (size_t)(ob + j) * MK + 2 * lane) = make_float2(a[j][0], a[j][1]);
        ss[j] = a[j][0] + a[j][1];
        qq[j] = a[j][0] * a[j][0] + a[j][1] * a[j][1];
    }
    #pragma unroll
    for (int o = 16; o; o >>= 1)
        #pragma unroll
        for (int j = 0; j < 8; j++) {
            ss[j] += __shfl_down_sync(0xffffffffu, ss[j], o);
            qq[j] += __shfl_down_sync(0xffffffffu, qq[j], o);
        }
    if (lane == 0)
        #pragma unroll
        for (int j = 0; j < 8; j++) { sS[ob + j] = ss[j]; sQ[ob + j] = qq[j]; }
    __syncthreads();
    if (tid < 64) { atomicAdd(&g_sum[tid], sS[tid]); atomicAdd(&g_sq[tid], sQ[tid]); }
    finalize_block(64, 1.0f / 524288.0f, 0, NB * M1, tid, 256);
}

// ---- convE: block = 64 outs (gridDim.y tiles) x 128 pts; weights via uniform LDG (L1);
//      x via LDS.128; acc packs output-pairs; 32-c chunks fully unrolled ----
#define CONVE_STEP(COFF, WOFF)                                                   \
    {                                                                            \
        float4 xv = *(const float4*)(xp + (COFF));                               \
        ull xa, xb, xc2, xd;                                                     \
        PACKF2(xa, xv.x, xv.x); PACKF2(xb, xv.y, xv.y);                          \
        PACKF2(xc2, xv.z, xv.z); PACKF2(xd, xv.w, xv.w);                         \
        ulonglong2 wA = *(const ulonglong2*)(wp + (WOFF));                       \
        ulonglong2 wB = *(const ulonglong2*)(wp + (WOFF) + 16);                  \
        FFMA2(acc[0][0], wA.x, xa); FFMA2(acc[1][0], wA.x, xb);                  \
        FFMA2(acc[2][0], wA.x, xc2); FFMA2(acc[3][0], wA.x, xd);                 \
        FFMA2(acc[0][1], wA.y, xa); FFMA2(acc[1][1], wA.y, xb);                  \
        FFMA2(acc[2][1], wA.y, xc2); FFMA2(acc[3][1], wA.y, xd);                 \
        FFMA2(acc[0][2], wB.x, xa); FFMA2(acc[1][2], wB.x, xb);                  \
        FFMA2(acc[2][2], wB.x, xc2); FFMA2(acc[3][2], wB.x, xd);                 \
        FFMA2(acc[0][3], wB.y, xa); FFMA2(acc[1][3], wB.y, xb);                  \
        FFMA2(acc[2][3], wB.y, xc2); FFMA2(acc[3][3], wB.y, xd);                 \
    }

template <int CIN, int WST, int DO_MAX>
__global__ __launch_bounds__(256) void convE(const float* __restrict__ in,
                                             const float* __restrict__ wtg,
                                             float* __restrict__ out,
                                             int npq, int normStart,
                                             int slotIn, int slotOut, float invN,
                                             int outC, int outChOff,
                                             int finCout, int gridTotal) {
    constexpr int CCH = 32;
    __shared__ float sx[CCH * 128];
    __shared__ float sNm[CIN], sRs[CIN];
    int tid = threadIdx.x, lane = tid & 31, w = tid >> 5;
    int p0g = blockIdx.x * 128;
    int b = p0g / npq, q0 = p0g - b * npq;
    int chW = blockIdx.y << 6;
    for (int c = tid; c < CIN; c += 256) {
        float mn = 0.0f, rs = 0.0f;
        if (c >= normStart) { mn = g_meanL[slotIn][c - normStart]; rs = g_rstdL[slotIn][c - normStart]; }
        sNm[c] = mn; sRs[c] = rs;
    }
    ull acc[4][4];
    #pragma unroll
    for (int p = 0; p < 4; p++)
        #pragma unroll
        for (int j = 0; j < 4; j++) acc[p][j] = 0ull;
    const float* inb = in + (size_t)b * CIN * npq + q0;
    const char* wbase = (const char*)wtg + ((size_t)chW + (size_t)w * 8) * 4;
    const float* xp = sx + 4 * lane;
    int c0 = 0;
    for (; c0 + CCH <= CIN; c0 += CCH) {
        __syncthreads();
        for (int i = tid; i < CCH * 128; i += 256) {
            int c = c0 + (i >> 7);
            float v = inb[(size_t)c * npq + (i & 127)];
            if (c >= normStart) v = fmaxf((v - sNm[c]) * sRs[c], 0.0f);
            sx[i] = v;
        }
        __syncthreads();
        const char* wp = wbase + (size_t)c0 * (WST * 4);
        #pragma unroll
        for (int c = 0; c < CCH; c++)
            CONVE_STEP(c << 7, c * (WST * 4))
    }
    if (c0 < CIN) {
        int cn = CIN - c0;
        __syncthreads();
        for (int i = tid; i < cn * 128; i += 256) {
            int c = c0 + (i >> 7);
            float v = inb[(size_t)c * npq + (i & 127)];
            if (c >= normStart) v = fmaxf((v - sNm[c]) * sRs[c], 0.0f);
            sx[i] = v;
        }
        __syncthreads();
        const char* wp = wbase + (size_t)c0 * (WST * 4);
        for (int c = 0; c < cn; c++)
            CONVE_STEP(c << 7, c * (WST * 4))
    }
    float f[4][8];
    #pragma unroll
    for (int p = 0; p < 4; p++)
        #pragma unroll
        for (int j = 0; j < 4; j++) UNPACKF2(f[p][2 * j], f[p][2 * j + 1], acc[p][j]);
    if (!DO_MAX) {
        int COUT = gridDim.y << 6;
        float* outb = out + ((size_t)b * COUT + chW + w * 8) * npq + q0 + 4 * lane;
        #pragma unroll
        for (int o = 0; o < 8; o++)
            *(float4*)(outb + (size_t)o * npq) = make_float4(f[0][o], f[1][o], f[2][o], f[3][o]);
    }
    float ss[8], qq[8];
    #pragma unroll
    for (int o = 0; o < 8; o++) {
        ss[o] = (f[0][o] + f[1][o]) + (f[2][o] + f[3][o]);
        qq[o] = (f[0][o] * f[0][o] + f[1][o] * f[1][o]) + (f[2][o] * f[2][o] + f[3][o] * f[3][o]);
    }
    #pragma unroll
    for (int o2 = 16; o2; o2 >>= 1)
        #pragma unroll
        for (int o = 0; o < 8; o++) {
            ss[o] += __shfl_down_sync(0xffffffffu, ss[o], o2);
            qq[o] += __shfl_down_sync(0xffffffffu, qq[o], o2);
        }
    if (lane == 0)
        #pragma unroll
        for (int o = 0; o < 8; o++) {
            atomicAdd(&g_sum[chW + w * 8 + o], ss[o]);
            atomicAdd(&g_sq[chW + w * 8 + o], qq[o]);
        }
    if (DO_MAX) {
        float mx[8];
        #pragma unroll
        for (int o = 0; o < 8; o++)
            mx[o] = fmaxf(fmaxf(f[0][o], f[1][o]), fmaxf(f[2][o], f[3][o]));
        #pragma unroll
        for (int o2 = 8; o2; o2 >>= 1)
            #pragma unroll
            for (int o = 0; o < 8; o++)
                mx[o] = fmaxf(mx[o], __shfl_down_sync(0xffffffffu, mx[o], o2));
        if ((lane & 15) == 0) {
            int MM = npq >> 6;
            int m = (q0 >> 6) + (lane >> 4);
            #pragma unroll
            for (int o = 0; o < 8; o++)
                out[((size_t)b * outC + outChOff + chW + w * 8 + o) * MM + m] = mx[o];
        }
    }
    finalize_block(finCout, invN, slotOut, gridTotal, tid, 256);
}

__global__ __launch_bounds__(128) void bx2_k() {
    int bm = blockIdx.x, b = bm >> 5, m = bm & 31, tid = threadIdx.x;
    __shared__ int sn[64]; __shared__ float sc2[3];
    if (tid < 64) sn[tid] = g_n2[bm * 64 + tid];
    if (tid < 3) sc2[tid] = g_c2[((size_t)b * M2 + m) * 3 + tid];
    __syncthreads();
    for (int i = tid; i < 131 * 64; i += 128) {
        int c = i >> 6, k = i & 63, n = sn[k];
        float v;
        if (c < 3) v = g_c1[((size_t)b * M1 + n) * 3 + c] - sc2[c];
        else {
            float z = g_f1[((size_t)b * 128 + (c - 3)) * M1 + n];
            v = fmaxf((z - g_meanL[2][c - 3]) * g_rstdL[2][c - 3], 0.0f);
        }
        g_bufB[(((size_t)b * 131 + c) * M2 + m) * 64 + k] = v;
    }
}

__global__ __launch_bounds__(256) void conv1_k(const float* __restrict__ in,
                                               const float* __restrict__ wt,
                                               float* __restrict__ out,
                                               int Cin, int Cout,
                                               int normStart, int slotIn,
                                               int slotOut, float invN) {
    extern __shared__ float s_in[];
    int nOc = Cout >> 7;
    int b = blockIdx.x / nOc, oc = blockIdx.x - b * nOc;
    int tid = threadIdx.x, lane = tid & 31, wp = tid >> 5;
    const float* inb = in + (size_t)b * Cin * 32;
    for (int i = tid; i < Cin * 32; i += 256) {
        int c = i >> 5;
        float v = inb[i];
        if (c >= normStart) v = fmaxf((v - g_meanL[slotIn][c - normStart]) * g_rstdL[slotIn][c - normStart], 0.0f);
        s_in[i] = v;
    }
    __syncthreads();
    float* outb = out + (size_t)b * Cout * 32;
    for (int ob = oc * 128 + wp * 8; ob < oc * 128 + 128; ob += 64) {
        float a[8];
        #pragma unroll
        for (int j = 0; j < 8; j++) a[j] = 0.0f;
        const float4* wp4 = (const float4*)(wt + ob);
        int cstep = Cout >> 2;
        #pragma unroll 4
        for (int c = 0; c < Cin; c++) {
            float x = s_in[(c << 5) + lane];
            float4 w0 = wp4[c * cstep];
            float4 w1 = wp4[c * cstep + 1];
            a[0] += w0.x * x; a[1] += w0.y * x; a[2] += w0.z * x; a[3] += w0.w * x;
            a[4] += w1.x * x; a[5] += w1.y * x; a[6] += w1.z * x; a[7] += w1.w * x;
        }
        float qq[8];
        #pragma unroll
        for (int j = 0; j < 8; j++) {
            outb[(ob + j) * 32 + lane] = a[j];
            qq[j] = a[j] * a[j];
        }
        #pragma unroll
        for (int o = 16; o; o >>= 1)
            #pragma unroll
            for (int j = 0; j < 8; j++) {
                a[j] += __shfl_down_sync(0xffffffffu, a[j], o);
                qq[j] += __shfl_down_sync(0xffffffffu, qq[j], o);
            }
        if (lane == 0)
            #pragma unroll
            for (int j = 0; j < 8; j++) {
                atomicAdd(&g_sum[ob + j], a[j]); atomicAdd(&g_sq[ob + j], qq[j]);
            }
    }
    finalize_block(Cout, invN, slotOut, NB * nOc, tid, 256);
}

__global__ void cc2_k() {
    int b = blockIdx.x, t = threadIdx.x;
    if (t < 96) {
        int c = t / 32, m = t % 32;
        g_x3[((size_t)(b * 259 + c)) * 32 + m] = g_c2[((size_t)b * 32 + m) * 3 + c];
    }
}

__global__ void mp3_k(const float* __restrict__ in, const float* __restrict__ oneh) {
    int b = blockIdx.x, o = threadIdx.x;
    const float* p = in + ((size_t)b * 512 + o) * 32;
    float v = p[0];
    #pragma unroll
    for (int m = 1; m < 32; m++) v = fmaxf(v, p[m]);
    g_xc[o * 64 + b] = fmaxf((v - g_meanL[8][o]) * g_rstdL[8][o], 0.0f);
    if (o < 3) g_xc[(512 + o) * 64 + b] = oneh[b * 3 + o];
}

__global__ void fc_k(const float* __restrict__ x, const float* __restrict__ w,
                     float* __restrict__ out, int Cin) {
    __shared__ float sm2[2], sqv[2];
    int o = blockIdx.x, b = threadIdx.x;
    const float* wr = w + (size_t)o * Cin;
    float z = 0.0f;
    for (int c = 0; c < Cin; c++) z += x[c * 64 + b] * wr[c];
    float s = z, q = z * z;
    #pragma unroll
    for (int off = 16; off; off >>= 1) {
        s += __shfl_down_sync(0xffffffffu, s, off);
        q += __shfl_down_sync(0xffffffffu, q, off);
    }
    if ((b & 31) == 0) { sm2[b >> 5] = s; sqv[b >> 5] = q; }
    __syncthreads();
    float mn = (sm2[0] + sm2[1]) * (1.0f / 64.0f);
    float vq = (sqv[0] + sqv[1]) * (1.0f / 64.0f);
    out[o * 64 + b] = fmaxf((z - mn) * rsqrtf(vq - mn * mn + 1e-5f), 0.0f);
}

__global__ void fco_k(const float* __restrict__ x, const float* __restrict__ w,
                      const float* __restrict__ bias, float* __restrict__ out) {
    int o = blockIdx.x, b = threadIdx.x;
    const float* wr = w + (size_t)o * 256;
    float z = bias[o];
    for (int c = 0; c < 256; c++) z += x[c * 64 + b] * wr[c];
    out[b * 59 + o] = z;
}

extern "C" void kernel_launch(void* const* d_in, const int* in_sizes, int n_in,
                              void* d_out, int out_size) {
    const float* coords = (const float*)d_in[0];
    const float* oneh   = (const float*)d_in[1];

    float *bufA, *bufB, *wt, *f1, *x3, *z3a, *z3b, *xc, *fa1, *fa2;
    cudaGetSymbolAddress((void**)&bufA, g_bufA);
    cudaGetSymbolAddress((void**)&bufB, g_bufB);
    cudaGetSymbolAddress((void**)&wt, g_wt);
    cudaGetSymbolAddress((void**)&f1, g_f1);
    cudaGetSymbolAddress((void**)&x3, g_x3);
    cudaGetSymbolAddress((void**)&z3a, g_z3a);
    cudaGetSymbolAddress((void**)&z3b, g_z3b);
    cudaGetSymbolAddress((void**)&xc, g_xc);
    cudaGetSymbolAddress((void**)&fa1, g_fa1);
    cudaGetSymbolAddress((void**)&fa2, g_fa2);

    // 0: fused fps + ball-query stage 1
    fpsbq1_k<<<NB, 1024>>>(coords);
    // 1: weight transposes
    tw_all<<<256, 256>>>((const float*)d_in[2], (const float*)d_in[3], (const float*)d_in[4],
                         (const float*)d_in[5], (const float*)d_in[6], (const float*)d_in[7],
                         (const float*)d_in[8], (const float*)d_in[9], (const float*)d_in[10]);
    // 2: gather + 3->64 conv (slot0)
    convA_k<<<NB * M1, 256>>>(coords, (const float*)d_in[2]);
    // 3: 64->64 conv (slot1) [ncu target]
    convE<64, 64, 0><<<dim3(4096, 1), 256>>>(bufA, wt + 192, bufB,
        8192, 0, 0, 1, 1.0f / 524288.0f, 0, 0, 64, 4096);
    // 4: 64->128 conv + fused maxpool -> f1 (slot2)
    convE<64, 128, 1><<<dim3(4096, 2), 256>>>(bufB, wt + 4288, f1,
        8192, 0, 1, 2, 1.0f / 524288.0f, 128, 0, 128, 8192);
    // 5-6: stage-2 sampling + input build
    fpsbq2_k<<<NB, 128>>>();
    bx2_k<<<NB * M2, 128>>>();
    // 7: 131->128 (no input norm, slot3)
    convE<131, 128, 0><<<dim3(1024, 2), 256>>>(bufB, wt + 12480, bufA,
        2048, 131, 0, 3, 1.0f / 131072.0f, 0, 0, 128, 2048);
    // 8: 128->128 (slot4)
    convE<128, 128, 0><<<dim3(1024, 2), 256>>>(bufA, wt + 29248, bufB,
        2048, 0, 3, 4, 1.0f / 131072.0f, 0, 0, 128, 2048);
    // 9: 128->256 + fused maxpool -> x3 (slot5)
    convE<128, 256, 1><<<dim3(1024, 4), 256>>>(bufB, wt + 45632, x3,
        2048, 0, 4, 5, 1.0f / 131072.0f, 259, 3, 256, 4096);
    // 10: centers into x3 channels 0-2
    cc2_k<<<NB, 96>>>();
    // 11-13: stage-3 convs
    conv1_k<<<NB * 2, 256, 259 * 32 * 4>>>(x3, wt + 78400, z3b, 259, 256, 3, 5, 6, 1.0f / 2048.0f);
    conv1_k<<<NB * 2, 256, 256 * 32 * 4>>>(z3b, wt + 144704, z3a, 256, 256, 0, 6, 7, 1.0f / 2048.0f);
    conv1_k<<<NB * 4, 256, 256 * 32 * 4>>>(z3a, wt + 210240, bufA, 256, 512, 0, 7, 8, 1.0f / 2048.0f);
    // 14: global max + onehot
    mp3_k<<<NB, 512>>>(bufA, oneh);
    // 15-17: FC head
    fc_k<<<512, 64>>>(xc, (const float*)d_in[11], fa1, 515);
    fc_k<<<256, 64>>>(fa1, (const float*)d_in[12], fa2, 512);
    fco_k<<<59, 64>>>(fa2, (const float*)d_in[13], (const float*)d_in[14], (float*)d_out);
}

// round 10
// speedup vs baseline: 1.3059x; 1.3059x over previous
#include <cuda_runtime.h>

#define NB 64
#define NP 1024
#define M1 128
#define M2 32

typedef unsigned long long ull;

#define PACKF2(d, lo, hi) asm("mov.b64 %0, {%1, %2};" : "=l"(d) : "f"(lo), "f"(hi))
#define UNPACKF2(lo, hi, d) asm("mov.b64 {%0, %1}, %2;" : "=f"(lo), "=f"(hi) : "l"(d))
#define FFMA2(acc, w, x) asm("fma.rn.f32x2 %0, %1, %2, %0;" : "+l"(acc) : "l"(w), "l"(x))

__device__ float g_bufA[(size_t)NB * 128 * M1 * 64];
__device__ float g_bufB[(size_t)NB * 128 * M1 * 64];
__device__ float g_f1[NB * 128 * M1];
__device__ float g_c1[NB * M1 * 3];
__device__ float g_c2[NB * M2 * 3];
__device__ int   g_i1[NB * M1];
__device__ int   g_i2[NB * M2];
__device__ int   g_n1[NB * M1 * 64];
__device__ int   g_n2[NB * M2 * 64];
__device__ float g_x3[NB * 259 * M2];
__device__ float g_z3a[NB * 512 * M2];
__device__ float g_z3b[NB * 256 * M2];
__device__ float g_xc[515 * NB];
__device__ float g_fa1[512 * NB];
__device__ float g_fa2[256 * NB];
__device__ __align__(16) float g_wt[350000];
__device__ float g_sum[512], g_sq[512];
__device__ float g_meanL[9][512], g_rstdL[9][512];
__device__ int   g_cnt;

__device__ __forceinline__ void finalize_block(int Cout, float invN, int slot,
                                               int gridTotal, int tid, int bdim) {
    __shared__ int s_last;
    __threadfence();
    __syncthreads();
    if (tid == 0) s_last = (atomicAdd(&g_cnt, 1) == gridTotal - 1) ? 1 : 0;
    __syncthreads();
    if (s_last) {
        for (int c = tid; c < Cout; c += bdim) {
            float s = __ldcg(&g_sum[c]), q = __ldcg(&g_sq[c]);
            float mn = s * invN;
            g_meanL[slot][c] = mn;
            g_rstdL[slot][c] = rsqrtf(q * invN - mn * mn + 1e-5f);
            g_sum[c] = 0.0f; g_sq[c] = 0.0f;
        }
        if (tid == 0) g_cnt = 0;
    }
}

__global__ void tw_all(const float* w1a, const float* w1b, const float* w1c,
                       const float* w2a, const float* w2b, const float* w2c,
                       const float* w3a, const float* w3b, const float* w3c) {
    const float* src[9] = { w1a, w1b, w1c, w2a, w2b, w2c, w3a, w3b, w3c };
    const int  O[9] = { 64, 64, 128, 128, 128, 256, 256, 256, 512 };
    const int  C[9] = { 3, 64, 64, 131, 128, 128, 259, 256, 256 };
    const int off[9] = { 0, 192, 4288, 12480, 29248, 45632, 78400, 144704, 210240 };
    int stride = gridDim.x * blockDim.x;
    int t0 = blockIdx.x * blockDim.x + threadIdx.x;
    for (int s = 0; s < 9; s++) {
        const float* W = src[s]; float* Wt = g_wt + off[s];
        int n = O[s] * C[s], Cs = C[s], Os = O[s];
        for (int i = t0; i < n; i += stride) {
            int o = i / Cs, c = i - o * Cs;
            Wt[c * Os + o] = W[i];
        }
    }
}

// ---- fused FPS(128) + ball-query for stage 1 ----
__global__ __launch_bounds__(1024) void fpsbq1_k(const float* __restrict__ coords) {
    __shared__ float sp[3 * NP];
    __shared__ float sv[32]; __shared__ int si[32];
    __shared__ float sc[3]; __shared__ int sfar;
    int b = blockIdx.x, t = threadIdx.x, lane = t & 31, w = t >> 5;
    const float* cb = coords + (size_t)b * 3 * NP;
    for (int i = t; i < 3 * NP; i += 1024) sp[i] = cb[i];
    __syncthreads();
    float px = sp[t], py = sp[NP + t], pz = sp[2 * NP + t];
    float dist = 1e10f; int far = 0;
    for (int s = 0; s < 128; s++) {
        if (t == far) {
            sc[0] = px; sc[1] = py; sc[2] = pz;
            g_i1[b * 128 + s] = far;
            float* cw = g_c1 + ((size_t)b * 128 + s) * 3;
            cw[0] = px; cw[1] = py; cw[2] = pz;
        }
        __syncthreads();
        float dx = __fadd_rn(px, -sc[0]), dy = __fadd_rn(py, -sc[1]), dz = __fadd_rn(pz, -sc[2]);
        float d = __fadd_rn(__fadd_rn(__fmul_rn(dx, dx), __fmul_rn(dy, dy)), __fmul_rn(dz, dz));
        dist = fminf(dist, d);
        float v = dist; int ii = t;
        #pragma unroll
        for (int o = 16; o; o >>= 1) {
            float ov = __shfl_down_sync(0xffffffffu, v, o);
            int oi = __shfl_down_sync(0xffffffffu, ii, o);
            if (ov > v || (ov == v && oi < ii)) { v = ov; ii = oi; }
        }
        if (lane == 0) { sv[w] = v; si[w] = ii; }
        __syncthreads();
        if (t < 32) {
            float v2 = sv[t]; int i2 = si[t];
            #pragma unroll
            for (int o = 16; o; o >>= 1) {
                float ov = __shfl_down_sync(0xffffffffu, v2, o);
                int oi = __shfl_down_sync(0xffffffffu, i2, o);
                if (ov > v2 || (ov == v2 && oi < i2)) { v2 = ov; i2 = oi; }
            }
            if (t == 0) sfar = i2;
        }
        __syncthreads();
        far = sfar;
    }
    __syncthreads();
    float r2 = (float)(0.2 * 0.2);
    for (int mi = 0; mi < 4; mi++) {
        int m = w * 4 + mi;
        const float* cr = g_c1 + ((size_t)b * 128 + m) * 3;
        float cx = cr[0], cy = cr[1], cz = cr[2];
        int base = (b * 128 + m) * 64, cnt = 0, firstj = -1;
        for (int ch = 0; ch < 32; ch++) {
            int j = (ch << 5) + lane;
            float dx = __fadd_rn(cx, -sp[j]);
            float dy = __fadd_rn(cy, -sp[NP + j]);
            float dz = __fadd_rn(cz, -sp[2 * NP + j]);
            float d = __fadd_rn(__fadd_rn(__fmul_rn(dx, dx), __fmul_rn(dy, dy)), __fmul_rn(dz, dz));
            bool hit = d < r2;
            unsigned mask = __ballot_sync(0xffffffffu, hit);
            int pos = cnt + __popc(mask & ((1u << lane) - 1u));
            if (hit && pos < 64) g_n1[base + pos] = j;
            if (firstj < 0 && mask) firstj = (ch << 5) + __ffs(mask) - 1;
            cnt += __popc(mask);
            if (cnt >= 64) break;
        }
        for (int s2 = cnt + lane; s2 < 64; s2 += 32) g_n1[base + s2] = firstj;
    }
}

// ---- fused FPS(32) + ball-query for stage 2 ----
__global__ __launch_bounds__(128) void fpsbq2_k() {
    __shared__ float sp[3 * 128];
    __shared__ float sv[4]; __shared__ int si[4];
    __shared__ float sc[3]; __shared__ int sfar;
    int b = blockIdx.x, t = threadIdx.x, lane = t & 31, w = t >> 5;
    for (int i = t; i < 384; i += 128) {
        int c = i >> 7, j = i & 127;
        sp[i] = g_c1[((size_t)b * 128 + j) * 3 + c];
    }
    __syncthreads();
    float px = sp[t], py = sp[128 + t], pz = sp[256 + t];
    float dist = 1e10f; int far = 0;
    for (int s = 0; s < 32; s++) {
        if (t == far) {
            sc[0] = px; sc[1] = py; sc[2] = pz;
            g_i2[b * 32 + s] = far;
            float* cw = g_c2 + ((size_t)b * 32 + s) * 3;
            cw[0] = px; cw[1] = py; cw[2] = pz;
        }
        __syncthreads();
        float dx = __fadd_rn(px, -sc[0]), dy = __fadd_rn(py, -sc[1]), dz = __fadd_rn(pz, -sc[2]);
        float d = __fadd_rn(__fadd_rn(__fmul_rn(dx, dx), __fmul_rn(dy, dy)), __fmul_rn(dz, dz));
        dist = fminf(dist, d);
        float v = dist; int ii = t;
        #pragma unroll
        for (int o = 16; o; o >>= 1) {
            float ov = __shfl_down_sync(0xffffffffu, v, o);
            int oi = __shfl_down_sync(0xffffffffu, ii, o);
            if (ov > v || (ov == v && oi < ii)) { v = ov; ii = oi; }
        }
        if (lane == 0) { sv[w] = v; si[w] = ii; }
        __syncthreads();
        if (t < 32) {
            float v2 = (t < 4) ? sv[t] : -1.0f;
            int i2 = (t < 4) ? si[t] : 0x7fffffff;
            #pragma unroll
            for (int o = 16; o; o >>= 1) {
                float ov = __shfl_down_sync(0xffffffffu, v2, o);
                int oi = __shfl_down_sync(0xffffffffu, i2, o);
                if (ov > v2 || (ov == v2 && oi < i2)) { v2 = ov; i2 = oi; }
            }
            if (t == 0) sfar = i2;
        }
        __syncthreads();
        far = sfar;
    }
    __syncthreads();
    float r2 = (float)(0.4 * 0.4);
    for (int mi = 0; mi < 8; mi++) {
        int m = w * 8 + mi;
        const float* cr = g_c2 + ((size_t)b * 32 + m) * 3;
        float cx = cr[0], cy = cr[1], cz = cr[2];
        int base = (b * 32 + m) * 64, cnt = 0, firstj = -1;
        for (int ch = 0; ch < 4; ch++) {
            int j = (ch << 5) + lane;
            float dx = __fadd_rn(cx, -sp[j]);
            float dy = __fadd_rn(cy, -sp[128 + j]);
            float dz = __fadd_rn(cz, -sp[256 + j]);
            float d = __fadd_rn(__fadd_rn(__fmul_rn(dx, dx), __fmul_rn(dy, dy)), __fmul_rn(dz, dz));
            bool hit = d < r2;
            unsigned mask = __ballot_sync(0xffffffffu, hit);
            int pos = cnt + __popc(mask & ((1u << lane) - 1u));
            if (hit && pos < 64) g_n2[base + pos] = j;
            if (firstj < 0 && mask) firstj = (ch << 5) + __ffs(mask) - 1;
            cnt += __popc(mask);
            if (cnt >= 64) break;
        }
        for (int s2 = cnt + lane; s2 < 64; s2 += 32) g_n2[base + s2] = firstj;
    }
}

// ---- stage-1 layer-1: fused gather + 3->64 conv, smem stats, finalize slot0 ----
__global__ __launch_bounds__(256) void convA_k(const float* __restrict__ coords,
                                               const float* __restrict__ w1a) {
    __shared__ float s_in[3 * 64];
    __shared__ float sW[3][64];
    __shared__ int sn[64];
    __shared__ float scx[3];
    __shared__ float sS[64], sQ[64];
    int bm = blockIdx.x, b = bm >> 7, m = bm & 127;
    int tid = threadIdx.x, lane = tid & 31, wp = tid >> 5;
    if (tid < 64) { sn[tid] = g_n1[bm * 64 + tid]; sS[tid] = 0.0f; sQ[tid] = 0.0f; }
    if (tid >= 64 && tid < 67) scx[tid - 64] = g_c1[((size_t)b * M1 + m) * 3 + (tid - 64)];
    if (tid >= 64 && tid < 256) {
        int i = tid - 64;
        if (i < 192) { int o = i / 3, c = i - o * 3; sW[c][o] = w1a[i]; }
    }
    __syncthreads();
    if (tid < 192) {
        int c = tid >> 6, k = tid & 63;
        s_in[c * 64 + k] = coords[(size_t)b * 3 * NP + c * NP + sn[k]] - scx[c];
    }
    __syncthreads();
    int ob = wp * 8;
    float a[8][2];
    #pragma unroll
    for (int j = 0; j < 8; j++) { a[j][0] = 0.0f; a[j][1] = 0.0f; }
    const float2* xrow = (const float2*)s_in + lane;
    #pragma unroll
    for (int c = 0; c < 3; c++) {
        float2 xv = xrow[c * 32];
        float4 w0 = *(const float4*)&sW[c][ob];
        float4 w1 = *(const float4*)&sW[c][ob + 4];
        float wv[8] = { w0.x, w0.y, w0.z, w0.w, w1.x, w1.y, w1.z, w1.w };
        #pragma unroll
        for (int j = 0; j < 8; j++) { a[j][0] += wv[j] * xv.x; a[j][1] += wv[j] * xv.y; }
    }
    size_t MK = (size_t)M1 * 64;
    float* outb = g_bufA + (size_t)b * 64 * MK + (size_t)m * 64;
    float ss[8], qq[8];
    #pragma unroll
    for (int j = 0; j < 8; j++) {
        *(float2*)(outb + (size_t)(ob + j) * MK + 2 * lane) = make_float2(a[j][0], a[j][1]);
        ss[j] = a[j][0] + a[j][1];
        qq[j] = a[j][0] * a[j][0] + a[j][1] * a[j][1];
    }
    #pragma unroll
    for (int o = 16; o; o >>= 1)
        #pragma unroll
        for (int j = 0; j < 8; j++) {
            ss[j] += __shfl_down_sync(0xffffffffu, ss[j], o);
            qq[j] += __shfl_down_sync(0xffffffffu, qq[j], o);
        }
    if (lane == 0)
        #pragma unroll
        for (int j = 0; j < 8; j++) { sS[ob + j] = ss[j]; sQ[ob + j] = qq[j]; }
    __syncthreads();
    if (tid < 64) { atomicAdd(&g_sum[tid], sS[tid]); atomicAdd(&g_sq[tid], sQ[tid]); }
    finalize_block(64, 1.0f / 524288.0f, 0, NB * M1, tid, 256);
}

// ---- stage-1 layer-2: 64->64 GEMM; f32x2; 2 m per block; stats -> slot1 ----
__global__ __launch_bounds__(256) void convB_k(const float* __restrict__ w1b) {
    extern __shared__ float sm[];
    float* s_in = sm;                 // 2 * 4096
    float* sW   = sm + 8192;          // 4096 : sW[c*64+o]
    float* sS   = sW + 4096;          // 2*64
    float* sQ   = sS + 128;           // 2*64
    float* sNm  = sQ + 128;           // 64
    float* sRs  = sNm + 64;           // 64
    int bm2 = blockIdx.x;
    int b = bm2 >> 6, mbase = (bm2 & 63) * 2;
    int tid = threadIdx.x, lane = tid & 31, wp = tid >> 5;
    int ml = wp >> 2, ob = (wp & 3) * 16;
    if (tid < 64) { sNm[tid] = g_meanL[0][tid]; sRs[tid] = g_rstdL[0][tid]; }
    if (tid < 128) { sS[tid] = 0.0f; sQ[tid] = 0.0f; }
    __syncthreads();
    size_t MK = (size_t)M1 * 64;
    const float* inb = g_bufA + (size_t)b * 64 * MK + (size_t)mbase * 64;
    for (int i = tid; i < 8192; i += 256) {
        int mloc = i >> 12, r = i & 4095, c = r >> 6, k = r & 63;
        float v = inb[(size_t)c * MK + mloc * 64 + k];
        s_in[i] = fmaxf((v - sNm[c]) * sRs[c], 0.0f);
    }
    for (int i = tid; i < 4096; i += 256) {
        int o = i >> 6, c = i & 63;
        sW[c * 64 + o] = w1b[i];
    }
    __syncthreads();
    ull acc[8][2];
    #pragma unroll
    for (int j = 0; j < 8; j++) { acc[j][0] = 0ull; acc[j][1] = 0ull; }
    const float2* xrow = (const float2*)(s_in + ml * 4096) + lane;
    #pragma unroll 4
    for (int c = 0; c < 64; c++) {
        float2 xv = xrow[c * 32];
        ull d0, d1;
        PACKF2(d0, xv.x, xv.x); PACKF2(d1, xv.y, xv.y);
        const ulonglong2* wr = (const ulonglong2*)(sW + c * 64 + ob);
        ulonglong2 w01 = wr[0], w23 = wr[1], w45 = wr[2], w67 = wr[3];
        FFMA2(acc[0][0], w01.x, d0); FFMA2(acc[0][1], w01.x, d1);
        FFMA2(acc[1][0], w01.y, d0); FFMA2(acc[1][1], w01.y, d1);
        FFMA2(acc[2][0], w23.x, d0); FFMA2(acc[2][1], w23.x, d1);
        FFMA2(acc[3][0], w23.y, d0); FFMA2(acc[3][1], w23.y, d1);
        FFMA2(acc[4][0], w45.x, d0); FFMA2(acc[4][1], w45.x, d1);
        FFMA2(acc[5][0], w45.y, d0); FFMA2(acc[5][1], w45.y, d1);
        FFMA2(acc[6][0], w67.x, d0); FFMA2(acc[6][1], w67.x, d1);
        FFMA2(acc[7][0], w67.y, d0); FFMA2(acc[7][1], w67.y, d1);
    }
    float a[16][2];
    #pragma unroll
    for (int j = 0; j < 8; j++) {
        UNPACKF2(a[2 * j][0], a[2 * j + 1][0], acc[j][0]);
        UNPACKF2(a[2 * j][1], a[2 * j + 1][1], acc[j][1]);
    }
    float* outb = g_bufB + (size_t)b * 64 * MK + (size_t)(mbase + ml) * 64;
    float ss[16], qq[16];
    #pragma unroll
    for (int j = 0; j < 16; j++) {
        *(float2*)(outb + (size_t)(ob + j) * MK + 2 * lane) = make_float2(a[j][0], a[j][1]);
        ss[j] = a[j][0] + a[j][1];
        qq[j] = a[j][0] * a[j][0] + a[j][1] * a[j][1];
    }
    #pragma unroll
    for (int o = 16; o; o >>= 1)
        #pragma unroll
        for (int j = 0; j < 16; j++) {
            ss[j] += __shfl_down_sync(0xffffffffu, ss[j], o);
            qq[j] += __shfl_down_sync(0xffffffffu, qq[j], o);
        }
    if (lane == 0)
        #pragma unroll
        for (int j = 0; j < 16; j++) { sS[ml * 64 + ob + j] = ss[j]; sQ[ml * 64 + ob + j] = qq[j]; }
    __syncthreads();
    if (tid < 64) {
        atomicAdd(&g_sum[tid], sS[tid] + sS[64 + tid]);
        atomicAdd(&g_sq[tid], sQ[tid] + sQ[64 + tid]);
    }
    finalize_block(64, 1.0f / 524288.0f, 1, NB * M1 / 2, tid, 256);
}

// ---- convT (R6 inner loop, WCH=64 for higher occupancy) ----
template <int CIN, int COUT, int MM, int DO_MAX>
__global__ __launch_bounds__(256) void convT(const float* __restrict__ in,
                                             const float* __restrict__ wtg,
                                             float* __restrict__ out,
                                             int normStart, int slotIn, int slotOut,
                                             float invN, int outC, int chOff) {
    constexpr int WCH = 64;
    extern __shared__ float sm[];
    float* s_in = sm;
    float* sW = s_in + CIN * 64;
    float* sS = sW + CIN * WCH;
    float* sQ = sS + COUT;
    float* sNm = sQ + COUT;
    float* sRs = sNm + CIN;
    int bm = blockIdx.x, b = bm / MM, m = bm - b * MM;
    int tid = threadIdx.x, lane = tid & 31, wp = tid >> 5;
    size_t MK = (size_t)MM * 64;
    for (int c = tid; c < CIN; c += 256) {
        float mn = 0.0f, rs = 0.0f;
        if (c >= normStart) { mn = g_meanL[slotIn][c - normStart]; rs = g_rstdL[slotIn][c - normStart]; }
        sNm[c] = mn; sRs[c] = rs;
    }
    for (int c = tid; c < COUT; c += 256) { sS[c] = 0.0f; sQ[c] = 0.0f; }
    __syncthreads();
    const float* inb = in + (size_t)b * CIN * MK + (size_t)m * 64;
    for (int i = tid; i < CIN * 64; i += 256) {
        int c = i >> 6;
        float v = inb[(size_t)c * MK + (i & 63)];
        if (c >= normStart) v = fmaxf((v - sNm[c]) * sRs[c], 0.0f);
        s_in[i] = v;
    }
    float* outb = out + (size_t)b * COUT * MK + (size_t)m * 64;
    const float2* xrow = (const float2*)s_in + lane;
    #pragma unroll
    for (int ch0 = 0; ch0 < COUT; ch0 += WCH) {
        __syncthreads();
        for (int i = tid; i < CIN * WCH; i += 256) {
            int c = i >> 6, o = i & 63;
            sW[i] = wtg[(size_t)c * COUT + ch0 + o];
        }
        __syncthreads();
        int ob = wp * 8;
        ull acc[4][2];
        #pragma unroll
        for (int j = 0; j < 4; j++) { acc[j][0] = 0ull; acc[j][1] = 0ull; }
        #pragma unroll 8
        for (int c = 0; c < CIN; c++) {
            float2 xv = xrow[c * 32];
            ull d0, d1;
            PACKF2(d0, xv.x, xv.x); PACKF2(d1, xv.y, xv.y);
            const ull* wr = (const ull*)(sW + (c << 6) + ob);
            ull W0 = wr[0], W1 = wr[1], W2 = wr[2], W3 = wr[3];
            FFMA2(acc[0][0], W0, d0); FFMA2(acc[0][1], W0, d1);
            FFMA2(acc[1][0], W1, d0); FFMA2(acc[1][1], W1, d1);
            FFMA2(acc[2][0], W2, d0); FFMA2(acc[2][1], W2, d1);
            FFMA2(acc[3][0], W3, d0); FFMA2(acc[3][1], W3, d1);
        }
        float a[8][2];
        #pragma unroll
        for (int j = 0; j < 4; j++) {
            UNPACKF2(a[2 * j][0], a[2 * j + 1][0], acc[j][0]);
            UNPACKF2(a[2 * j][1], a[2 * j + 1][1], acc[j][1]);
        }
        int gob = ch0 + ob;
        float ss[8], qq[8], mmx[8];
        #pragma unroll
        for (int j = 0; j < 8; j++) {
            if (!DO_MAX)
                *(float2*)(outb + (size_t)(gob + j) * MK + 2 * lane) = make_float2(a[j][0], a[j][1]);
            ss[j] = a[j][0] + a[j][1];
            qq[j] = a[j][0] * a[j][0] + a[j][1] * a[j][1];
            mmx[j] = fmaxf(a[j][0], a[j][1]);
        }
        #pragma unroll
        for (int o = 16; o; o >>= 1)
            #pragma unroll
            for (int j = 0; j < 8; j++) {
                ss[j] += __shfl_down_sync(0xffffffffu, ss[j], o);
                qq[j] += __shfl_down_sync(0xffffffffu, qq[j], o);
                if (DO_MAX) mmx[j] = fmaxf(mmx[j], __shfl_down_sync(0xffffffffu, mmx[j], o));
            }
        if (lane == 0)
            #pragma unroll
            for (int j = 0; j < 8; j++) {
                sS[gob + j] = ss[j]; sQ[gob + j] = qq[j];
                if (DO_MAX)
                    out[((size_t)b * outC + chOff + gob + j) * MM + m] = mmx[j];
            }
    }
    __syncthreads();
    for (int c = tid; c < COUT; c += 256) { atomicAdd(&g_sum[c], sS[c]); atomicAdd(&g_sq[c], sQ[c]); }
    finalize_block(COUT, invN, slotOut, NB * MM, tid, 256);
}

__global__ __launch_bounds__(128) void bx2_k() {
    int bm = blockIdx.x, b = bm >> 5, m = bm & 31, tid = threadIdx.x;
    __shared__ int sn[64]; __shared__ float sc2[3];
    if (tid < 64) sn[tid] = g_n2[bm * 64 + tid];
    if (tid < 3) sc2[tid] = g_c2[((size_t)b * M2 + m) * 3 + tid];
    __syncthreads();
    for (int i = tid; i < 131 * 64; i += 128) {
        int c = i >> 6, k = i & 63, n = sn[k];
        float v;
        if (c < 3) v = g_c1[((size_t)b * M1 + n) * 3 + c] - sc2[c];
        else {
            float z = g_f1[((size_t)b * 128 + (c - 3)) * M1 + n];
            v = fmaxf((z - g_meanL[2][c - 3]) * g_rstdL[2][c - 3], 0.0f);
        }
        g_bufB[(((size_t)b * 131 + c) * M2 + m) * 64 + k] = v;
    }
}

__global__ __launch_bounds__(256) void conv1_k(const float* __restrict__ in,
                                               const float* __restrict__ wt,
                                               float* __restrict__ out,
                                               int Cin, int Cout,
                                               int normStart, int slotIn,
                                               int slotOut, float invN) {
    extern __shared__ float s_in[];
    int nOc = Cout >> 7;
    int b = blockIdx.x / nOc, oc = blockIdx.x - b * nOc;
    int tid = threadIdx.x, lane = tid & 31, wp = tid >> 5;
    const float* inb = in + (size_t)b * Cin * 32;
    for (int i = tid; i < Cin * 32; i += 256) {
        int c = i >> 5;
        float v = inb[i];
        if (c >= normStart) v = fmaxf((v - g_meanL[slotIn][c - normStart]) * g_rstdL[slotIn][c - normStart], 0.0f);
        s_in[i] = v;
    }
    __syncthreads();
    float* outb = out + (size_t)b * Cout * 32;
    for (int ob = oc * 128 + wp * 8; ob < oc * 128 + 128; ob += 64) {
        float a[8];
        #pragma unroll
        for (int j = 0; j < 8; j++) a[j] = 0.0f;
        const float4* wp4 = (const float4*)(wt + ob);
        int cstep = Cout >> 2;
        #pragma unroll 4
        for (int c = 0; c < Cin; c++) {
            float x = s_in[(c << 5) + lane];
            float4 w0 = wp4[c * cstep];
            float4 w1 = wp4[c * cstep + 1];
            a[0] += w0.x * x; a[1] += w0.y * x; a[2] += w0.z * x; a[3] += w0.w * x;
            a[4] += w1.x * x; a[5] += w1.y * x; a[6] += w1.z * x; a[7] += w1.w * x;
        }
        float qq[8];
        #pragma unroll
        for (int j = 0; j < 8; j++) {
            outb[(ob + j) * 32 + lane] = a[j];
            qq[j] = a[j] * a[j];
        }
        #pragma unroll
        for (int o = 16; o; o >>= 1)
            #pragma unroll
            for (int j = 0; j < 8; j++) {
                a[j] += __shfl_down_sync(0xffffffffu, a[j], o);
                qq[j] += __shfl_down_sync(0xffffffffu, qq[j], o);
            }
        if (lane == 0)
            #pragma unroll
            for (int j = 0; j < 8; j++) {
                atomicAdd(&g_sum[ob + j], a[j]); atomicAdd(&g_sq[ob + j], qq[j]);
            }
    }
    finalize_block(Cout, invN, slotOut, NB * nOc, tid, 256);
}

__global__ void cc2_k() {
    int b = blockIdx.x, t = threadIdx.x;
    if (t < 96) {
        int c = t / 32, m = t % 32;
        g_x3[((size_t)(b * 259 + c)) * 32 + m] = g_c2[((size_t)b * 32 + m) * 3 + c];
    }
}

__global__ void mp3_k(const float* __restrict__ in, const float* __restrict__ oneh) {
    int b = blockIdx.x, o = threadIdx.x;
    const float* p = in + ((size_t)b * 512 + o) * 32;
    float v = p[0];
    #pragma unroll
    for (int m = 1; m < 32; m++) v = fmaxf(v, p[m]);
    g_xc[o * 64 + b] = fmaxf((v - g_meanL[8][o]) * g_rstdL[8][o], 0.0f);
    if (o < 3) g_xc[(512 + o) * 64 + b] = oneh[b * 3 + o];
}

__global__ void fc_k(const float* __restrict__ x, const float* __restrict__ w,
                     float* __restrict__ out, int Cin) {
    __shared__ float sm2[2], sqv[2];
    int o = blockIdx.x, b = threadIdx.x;
    const float* wr = w + (size_t)o * Cin;
    float z = 0.0f;
    for (int c = 0; c < Cin; c++) z += x[c * 64 + b] * wr[c];
    float s = z, q = z * z;
    #pragma unroll
    for (int off = 16; off; off >>= 1) {
        s += __shfl_down_sync(0xffffffffu, s, off);
        q += __shfl_down_sync(0xffffffffu, q, off);
    }
    if ((b & 31) == 0) { sm2[b >> 5] = s; sqv[b >> 5] = q; }
    __syncthreads();
    float mn = (sm2[0] + sm2[1]) * (1.0f / 64.0f);
    float vq = (sqv[0] + sqv[1]) * (1.0f / 64.0f);
    out[o * 64 + b] = fmaxf((z - mn) * rsqrtf(vq - mn * mn + 1e-5f), 0.0f);
}

__global__ void fco_k(const float* __restrict__ x, const float* __restrict__ w,
                      const float* __restrict__ bias, float* __restrict__ out) {
    int o = blockIdx.x, b = threadIdx.x;
    const float* wr = w + (size_t)o * 256;
    float z = bias[o];
    for (int c = 0; c < 256; c++) z += x[c * 64 + b] * wr[c];
    out[b * 59 + o] = z;
}

extern "C" void kernel_launch(void* const* d_in, const int* in_sizes, int n_in,
                              void* d_out, int out_size) {
    const float* coords = (const float*)d_in[0];
    const float* oneh   = (const float*)d_in[1];

    float *bufA, *bufB, *wt, *f1, *x3, *z3a, *z3b, *xc, *fa1, *fa2;
    cudaGetSymbolAddress((void**)&bufA, g_bufA);
    cudaGetSymbolAddress((void**)&bufB, g_bufB);
    cudaGetSymbolAddress((void**)&wt, g_wt);
    cudaGetSymbolAddress((void**)&f1, g_f1);
    cudaGetSymbolAddress((void**)&x3, g_x3);
    cudaGetSymbolAddress((void**)&z3a, g_z3a);
    cudaGetSymbolAddress((void**)&z3b, g_z3b);
    cudaGetSymbolAddress((void**)&xc, g_xc);
    cudaGetSymbolAddress((void**)&fa1, g_fa1);
    cudaGetSymbolAddress((void**)&fa2, g_fa2);

    const int smemB    = (8192 + 4096 + 256 + 128) * 4;
    const int sm_64    = (64 * 64 + 64 * 64 + 2 * 128 + 2 * 64) * 4;
    const int sm_131   = (131 * 64 + 131 * 64 + 2 * 128 + 2 * 131) * 4;
    const int sm_128a  = (128 * 64 + 128 * 64 + 2 * 128 + 2 * 128) * 4;
    const int sm_128b  = (128 * 64 + 128 * 64 + 2 * 256 + 2 * 128) * 4;
    cudaFuncSetAttribute(convB_k, cudaFuncAttributeMaxDynamicSharedMemorySize, smemB);
    cudaFuncSetAttribute(convT<64, 128, M1, 1>, cudaFuncAttributeMaxDynamicSharedMemorySize, sm_64);
    cudaFuncSetAttribute(convT<131, 128, M2, 0>, cudaFuncAttributeMaxDynamicSharedMemorySize, sm_131);
    cudaFuncSetAttribute(convT<128, 128, M2, 0>, cudaFuncAttributeMaxDynamicSharedMemorySize, sm_128a);
    cudaFuncSetAttribute(convT<128, 256, M2, 1>, cudaFuncAttributeMaxDynamicSharedMemorySize, sm_128b);

    // 0: fused fps + ball-query stage 1
    fpsbq1_k<<<NB, 1024>>>(coords);
    // 1: weight transposes
    tw_all<<<256, 256>>>((const float*)d_in[2], (const float*)d_in[3], (const float*)d_in[4],
                         (const float*)d_in[5], (const float*)d_in[6], (const float*)d_in[7],
                         (const float*)d_in[8], (const float*)d_in[9], (const float*)d_in[10]);
    // 2: gather + 3->64 conv (slot0)
    convA_k<<<NB * M1, 256>>>(coords, (const float*)d_in[2]);
    // 3: 64->64 conv (slot1) [ncu target]
    convB_k<<<NB * M1 / 2, 256, smemB>>>((const float*)d_in[3]);
    // 4: 64->128 conv + fused maxpool -> f1 (slot2)
    convT<64, 128, M1, 1><<<NB * M1, 256, sm_64>>>(bufB, wt + 4288, f1, 0, 1, 2,
                                                   1.0f / 524288.0f, 128, 0);
    // 5-6: stage-2 sampling + input build
    fpsbq2_k<<<NB, 128>>>();
    bx2_k<<<NB * M2, 128>>>();
    // 7-9: stage-2 MLP
    convT<131, 128, M2, 0><<<NB * M2, 256, sm_131>>>(bufB, wt + 12480, bufA, 131, 0, 3,
                                                     1.0f / 131072.0f, 0, 0);
    convT<128, 128, M2, 0><<<NB * M2, 256, sm_128a>>>(bufA, wt + 29248, bufB, 0, 3, 4,
                                                      1.0f / 131072.0f, 0, 0);
    convT<128, 256, M2, 1><<<NB * M2, 256, sm_128b>>>(bufB, wt + 45632, x3, 0, 4, 5,
                                                      1.0f / 131072.0f, 259, 3);
    // 10: centers into x3 channels 0-2
    cc2_k<<<NB, 96>>>();
    // 11-13: stage-3 convs
    conv1_k<<<NB * 2, 256, 259 * 32 * 4>>>(x3, wt + 78400, z3b, 259, 256, 3, 5, 6, 1.0f / 2048.0f);
    conv1_k<<<NB * 2, 256, 256 * 32 * 4>>>(z3b, wt + 144704, z3a, 256, 256, 0, 6, 7, 1.0f / 2048.0f);
    conv1_k<<<NB * 4, 256, 256 * 32 * 4>>>(z3a, wt + 210240, bufA, 256, 512, 0, 7, 8, 1.0f / 2048.0f);
    // 14: global max + onehot
    mp3_k<<<NB, 512>>>(bufA, oneh);
    // 15-17: FC head
    fc_k<<<512, 64>>>(xc, (const float*)d_in[11], fa1, 515);
    fc_k<<<256, 64>>>(fa1, (const float*)d_in[12], fa2, 512);
    fco_k<<<59, 64>>>(fa2, (const float*)d_in[13], (const float*)d_in[14], (float*)d_out);
}

// round 12
// speedup vs baseline: 1.3281x; 1.0170x over previous
#include <cuda_runtime.h>

#define NB 64
#define NP 1024
#define M1 128
#define M2 32

typedef unsigned long long ull;

#define PACKF2(d, lo, hi) asm("mov.b64 %0, {%1, %2};" : "=l"(d) : "f"(lo), "f"(hi))
#define UNPACKF2(lo, hi, d) asm("mov.b64 {%0, %1}, %2;" : "=f"(lo), "=f"(hi) : "l"(d))
#define FFMA2(acc, w, x) asm("fma.rn.f32x2 %0, %1, %2, %0;" : "+l"(acc) : "l"(w), "l"(x))

__device__ float g_bufA[(size_t)NB * 128 * M1 * 64];
__device__ float g_bufB[(size_t)NB * 128 * M1 * 64];
__device__ float g_f1[NB * 128 * M1];
__device__ float g_c1[NB * M1 * 3];
__device__ float g_c2[NB * M2 * 3];
__device__ int   g_i1[NB * M1];
__device__ int   g_i2[NB * M2];
__device__ int   g_n1[NB * M1 * 64];
__device__ int   g_n2[NB * M2 * 64];
__device__ float g_x3[NB * 259 * M2];
__device__ float g_z3a[NB * 512 * M2];
__device__ float g_z3b[NB * 256 * M2];
__device__ float g_xc[515 * NB];
__device__ float g_fa1[512 * NB];
__device__ float g_fa2[256 * NB];
__device__ __align__(16) float g_wt[350000];
__device__ float g_sum[512], g_sq[512];
__device__ float g_meanL[9][512], g_rstdL[9][512];
__device__ int   g_cnt;

__device__ __forceinline__ void finalize_block(int Cout, float invN, int slot,
                                               int gridTotal, int tid, int bdim) {
    __shared__ int s_last;
    __threadfence();
    __syncthreads();
    if (tid == 0) s_last = (atomicAdd(&g_cnt, 1) == gridTotal - 1) ? 1 : 0;
    __syncthreads();
    if (s_last) {
        for (int c = tid; c < Cout; c += bdim) {
            float s = __ldcg(&g_sum[c]), q = __ldcg(&g_sq[c]);
            float mn = s * invN;
            g_meanL[slot][c] = mn;
            g_rstdL[slot][c] = rsqrtf(q * invN - mn * mn + 1e-5f);
            g_sum[c] = 0.0f; g_sq[c] = 0.0f;
        }
        if (tid == 0) g_cnt = 0;
    }
}

__global__ void tw_all(const float* w1a, const float* w1b, const float* w1c,
                       const float* w2a, const float* w2b, const float* w2c,
                       const float* w3a, const float* w3b, const float* w3c) {
    const float* src[9] = { w1a, w1b, w1c, w2a, w2b, w2c, w3a, w3b, w3c };
    const int  O[9] = { 64, 64, 128, 128, 128, 256, 256, 256, 512 };
    const int  C[9] = { 3, 64, 64, 131, 128, 128, 259, 256, 256 };
    const int off[9] = { 0, 192, 4288, 12480, 29248, 45632, 78400, 144704, 210240 };
    int stride = gridDim.x * blockDim.x;
    int t0 = blockIdx.x * blockDim.x + threadIdx.x;
    for (int s = 0; s < 9; s++) {
        const float* W = src[s]; float* Wt = g_wt + off[s];
        int n = O[s] * C[s], Cs = C[s], Os = O[s];
        for (int i = t0; i < n; i += stride) {
            int o = i / Cs, c = i - o * Cs;
            Wt[c * Os + o] = W[i];
        }
    }
}

// ---- fused FPS(128) + ball-query for stage 1 ----
__global__ __launch_bounds__(1024) void fpsbq1_k(const float* __restrict__ coords) {
    __shared__ float sp[3 * NP];
    __shared__ float sv[32]; __shared__ int si[32];
    __shared__ float sc[3]; __shared__ int sfar;
    int b = blockIdx.x, t = threadIdx.x, lane = t & 31, w = t >> 5;
    const float* cb = coords + (size_t)b * 3 * NP;
    for (int i = t; i < 3 * NP; i += 1024) sp[i] = cb[i];
    __syncthreads();
    float px = sp[t], py = sp[NP + t], pz = sp[2 * NP + t];
    float dist = 1e10f; int far = 0;
    for (int s = 0; s < 128; s++) {
        if (t == far) {
            sc[0] = px; sc[1] = py; sc[2] = pz;
            g_i1[b * 128 + s] = far;
            float* cw = g_c1 + ((size_t)b * 128 + s) * 3;
            cw[0] = px; cw[1] = py; cw[2] = pz;
        }
        __syncthreads();
        float dx = __fadd_rn(px, -sc[0]), dy = __fadd_rn(py, -sc[1]), dz = __fadd_rn(pz, -sc[2]);
        float d = __fadd_rn(__fadd_rn(__fmul_rn(dx, dx), __fmul_rn(dy, dy)), __fmul_rn(dz, dz));
        dist = fminf(dist, d);
        float v = dist; int ii = t;
        #pragma unroll
        for (int o = 16; o; o >>= 1) {
            float ov = __shfl_down_sync(0xffffffffu, v, o);
            int oi = __shfl_down_sync(0xffffffffu, ii, o);
            if (ov > v || (ov == v && oi < ii)) { v = ov; ii = oi; }
        }
        if (lane == 0) { sv[w] = v; si[w] = ii; }
        __syncthreads();
        if (t < 32) {
            float v2 = sv[t]; int i2 = si[t];
            #pragma unroll
            for (int o = 16; o; o >>= 1) {
                float ov = __shfl_down_sync(0xffffffffu, v2, o);
                int oi = __shfl_down_sync(0xffffffffu, i2, o);
                if (ov > v2 || (ov == v2 && oi < i2)) { v2 = ov; i2 = oi; }
            }
            if (t == 0) sfar = i2;
        }
        __syncthreads();
        far = sfar;
    }
    __syncthreads();
    float r2 = (float)(0.2 * 0.2);
    for (int mi = 0; mi < 4; mi++) {
        int m = w * 4 + mi;
        const float* cr = g_c1 + ((size_t)b * 128 + m) * 3;
        float cx = cr[0], cy = cr[1], cz = cr[2];
        int base = (b * 128 + m) * 64, cnt = 0, firstj = -1;
        for (int ch = 0; ch < 32; ch++) {
            int j = (ch << 5) + lane;
            float dx = __fadd_rn(cx, -sp[j]);
            float dy = __fadd_rn(cy, -sp[NP + j]);
            float dz = __fadd_rn(cz, -sp[2 * NP + j]);
            float d = __fadd_rn(__fadd_rn(__fmul_rn(dx, dx), __fmul_rn(dy, dy)), __fmul_rn(dz, dz));
            bool hit = d < r2;
            unsigned mask = __ballot_sync(0xffffffffu, hit);
            int pos = cnt + __popc(mask & ((1u << lane) - 1u));
            if (hit && pos < 64) g_n1[base + pos] = j;
            if (firstj < 0 && mask) firstj = (ch << 5) + __ffs(mask) - 1;
            cnt += __popc(mask);
            if (cnt >= 64) break;
        }
        for (int s2 = cnt + lane; s2 < 64; s2 += 32) g_n1[base + s2] = firstj;
    }
}

// ---- fused FPS(32) + ball-query for stage 2 ----
__global__ __launch_bounds__(128) void fpsbq2_k() {
    __shared__ float sp[3 * 128];
    __shared__ float sv[4]; __shared__ int si[4];
    __shared__ float sc[3]; __shared__ int sfar;
    int b = blockIdx.x, t = threadIdx.x, lane = t & 31, w = t >> 5;
    for (int i = t; i < 384; i += 128) {
        int c = i >> 7, j = i & 127;
        sp[i] = g_c1[((size_t)b * 128 + j) * 3 + c];
    }
    __syncthreads();
    float px = sp[t], py = sp[128 + t], pz = sp[256 + t];
    float dist = 1e10f; int far = 0;
    for (int s = 0; s < 32; s++) {
        if (t == far) {
            sc[0] = px; sc[1] = py; sc[2] = pz;
            g_i2[b * 32 + s] = far;
            float* cw = g_c2 + ((size_t)b * 32 + s) * 3;
            cw[0] = px; cw[1] = py; cw[2] = pz;
        }
        __syncthreads();
        float dx = __fadd_rn(px, -sc[0]), dy = __fadd_rn(py, -sc[1]), dz = __fadd_rn(pz, -sc[2]);
        float d = __fadd_rn(__fadd_rn(__fmul_rn(dx, dx), __fmul_rn(dy, dy)), __fmul_rn(dz, dz));
        dist = fminf(dist, d);
        float v = dist; int ii = t;
        #pragma unroll
        for (int o = 16; o; o >>= 1) {
            float ov = __shfl_down_sync(0xffffffffu, v, o);
            int oi = __shfl_down_sync(0xffffffffu, ii, o);
            if (ov > v || (ov == v && oi < ii)) { v = ov; ii = oi; }
        }
        if (lane == 0) { sv[w] = v; si[w] = ii; }
        __syncthreads();
        if (t < 32) {
            float v2 = (t < 4) ? sv[t] : -1.0f;
            int i2 = (t < 4) ? si[t] : 0x7fffffff;
            #pragma unroll
            for (int o = 16; o; o >>= 1) {
                float ov = __shfl_down_sync(0xffffffffu, v2, o);
                int oi = __shfl_down_sync(0xffffffffu, i2, o);
                if (ov > v2 || (ov == v2 && oi < i2)) { v2 = ov; i2 = oi; }
            }
            if (t == 0) sfar = i2;
        }
        __syncthreads();
        far = sfar;
    }
    __syncthreads();
    float r2 = (float)(0.4 * 0.4);
    for (int mi = 0; mi < 8; mi++) {
        int m = w * 8 + mi;
        const float* cr = g_c2 + ((size_t)b * 32 + m) * 3;
        float cx = cr[0], cy = cr[1], cz = cr[2];
        int base = (b * 32 + m) * 64, cnt = 0, firstj = -1;
        for (int ch = 0; ch < 4; ch++) {
            int j = (ch << 5) + lane;
            float dx = __fadd_rn(cx, -sp[j]);
            float dy = __fadd_rn(cy, -sp[128 + j]);
            float dz = __fadd_rn(cz, -sp[256 + j]);
            float d = __fadd_rn(__fadd_rn(__fmul_rn(dx, dx), __fmul_rn(dy, dy)), __fmul_rn(dz, dz));
            bool hit = d < r2;
            unsigned mask = __ballot_sync(0xffffffffu, hit);
            int pos = cnt + __popc(mask & ((1u << lane) - 1u));
            if (hit && pos < 64) g_n2[base + pos] = j;
            if (firstj < 0 && mask) firstj = (ch << 5) + __ffs(mask) - 1;
            cnt += __popc(mask);
            if (cnt >= 64) break;
        }
        for (int s2 = cnt + lane; s2 < 64; s2 += 32) g_n2[base + s2] = firstj;
    }
}

// ---- stage-1 layer-1: fused gather + 3->64 conv, smem stats, finalize slot0 ----
__global__ __launch_bounds__(256) void convA_k(const float* __restrict__ coords,
                                               const float* __restrict__ w1a) {
    __shared__ float s_in[3 * 64];
    __shared__ float sW[3][64];
    __shared__ int sn[64];
    __shared__ float scx[3];
    __shared__ float sS[64], sQ[64];
    int bm = blockIdx.x, b = bm >> 7, m = bm & 127;
    int tid = threadIdx.x, lane = tid & 31, wp = tid >> 5;
    if (tid < 64) { sn[tid] = g_n1[bm * 64 + tid]; sS[tid] = 0.0f; sQ[tid] = 0.0f; }
    if (tid >= 64 && tid < 67) scx[tid - 64] = g_c1[((size_t)b * M1 + m) * 3 + (tid - 64)];
    if (tid >= 64 && tid < 256) {
        int i = tid - 64;
        if (i < 192) { int o = i / 3, c = i - o * 3; sW[c][o] = w1a[i]; }
    }
    __syncthreads();
    if (tid < 192) {
        int c = tid >> 6, k = tid & 63;
        s_in[c * 64 + k] = coords[(size_t)b * 3 * NP + c * NP + sn[k]] - scx[c];
    }
    __syncthreads();
    int ob = wp * 8;
    float a[8][2];
    #pragma unroll
    for (int j = 0; j < 8; j++) { a[j][0] = 0.0f; a[j][1] = 0.0f; }
    const float2* xrow = (const float2*)s_in + lane;
    #pragma unroll
    for (int c = 0; c < 3; c++) {
        float2 xv = xrow[c * 32];
        float4 w0 = *(const float4*)&sW[c][ob];
        float4 w1 = *(const float4*)&sW[c][ob + 4];
        float wv[8] = { w0.x, w0.y, w0.z, w0.w, w1.x, w1.y, w1.z, w1.w };
        #pragma unroll
        for (int j = 0; j < 8; j++) { a[j][0] += wv[j] * xv.x; a[j][1] += wv[j] * xv.y; }
    }
    size_t MK = (size_t)M1 * 64;
    float* outb = g_bufA + (size_t)b * 64 * MK + (size_t)m * 64;
    float ss[8], qq[8];
    #pragma unroll
    for (int j = 0; j < 8; j++) {
        *(float2*)(outb + (size_t)(ob + j) * MK + 2 * lane) = make_float2(a[j][0], a[j][1]);
        ss[j] = a[j][0] + a[j][1];
        qq[j] = a[j][0] * a[j][0] + a[j][1] * a[j][1];
    }
    #pragma unroll
    for (int o = 16; o; o >>= 1)
        #pragma unroll
        for (int j = 0; j < 8; j++) {
            ss[j] += __shfl_down_sync(0xffffffffu, ss[j], o);
            qq[j] += __shfl_down_sync(0xffffffffu, qq[j], o);
        }
    if (lane == 0)
        #pragma unroll
        for (int j = 0; j < 8; j++) { sS[ob + j] = ss[j]; sQ[ob + j] = qq[j]; }
    __syncthreads();
    if (tid < 64) { atomicAdd(&g_sum[tid], sS[tid]); atomicAdd(&g_sq[tid], sQ[tid]); }
    finalize_block(64, 1.0f / 524288.0f, 0, NB * M1, tid, 256);
}

// ---- stage-1 layer-2 (R5 variant, stride 68): 64->64 GEMM, scalar FFMA, smem weights ----
__global__ __launch_bounds__(256) void convB_k(const float* __restrict__ w1b) {
    __shared__ float s_in[64 * 64];
    __shared__ float sW[64 * 68];
    __shared__ float sS[64], sQ[64];
    __shared__ float sNm[64], sRs[64];
    int bm = blockIdx.x, b = bm >> 7, m = bm & 127;
    int tid = threadIdx.x, lane = tid & 31, wp = tid >> 5;
    if (tid < 64) { sNm[tid] = g_meanL[0][tid]; sRs[tid] = g_rstdL[0][tid]; sS[tid] = 0.0f; sQ[tid] = 0.0f; }
    __syncthreads();
    size_t MK = (size_t)M1 * 64;
    const float* inb = g_bufA + (size_t)b * 64 * MK + (size_t)m * 64;
    for (int i = tid; i < 4096; i += 256) {
        int c = i >> 6, k = i & 63;
        float v = inb[(size_t)c * MK + k];
        s_in[i] = fmaxf((v - sNm[c]) * sRs[c], 0.0f);
        sW[k * 68 + c] = w1b[i];   // transpose: sW[cin*68 + cout], 68 % 4 == 0 -> float4-aligned
    }
    __syncthreads();
    int ob = wp * 8;
    float a[8][2];
    #pragma unroll
    for (int j = 0; j < 8; j++) { a[j][0] = 0.0f; a[j][1] = 0.0f; }
    const float2* xrow = (const float2*)s_in + lane;
    #pragma unroll 4
    for (int c = 0; c < 64; c++) {
        float2 xv = xrow[c * 32];
        float4 w0 = *(const float4*)&sW[c * 68 + ob];
        float4 w1 = *(const float4*)&sW[c * 68 + ob + 4];
        float wv[8] = { w0.x, w0.y, w0.z, w0.w, w1.x, w1.y, w1.z, w1.w };
        #pragma unroll
        for (int j = 0; j < 8; j++) { a[j][0] += wv[j] * xv.x; a[j][1] += wv[j] * xv.y; }
    }
    float* outb = g_bufB + (size_t)b * 64 * MK + (size_t)m * 64;
    float ss[8], qq[8];
    #pragma unroll
    for (int j = 0; j < 8; j++) {
        *(float2*)(outb + (size_t)(ob + j) * MK + 2 * lane) = make_float2(a[j][0], a[j][1]);
        ss[j] = a[j][0] + a[j][1];
        qq[j] = a[j][0] * a[j][0] + a[j][1] * a[j][1];
    }
    #pragma unroll
    for (int o = 16; o; o >>= 1)
        #pragma unroll
        for (int j = 0; j < 8; j++) {
            ss[j] += __shfl_down_sync(0xffffffffu, ss[j], o);
            qq[j] += __shfl_down_sync(0xffffffffu, qq[j], o);
        }
    if (lane == 0)
        #pragma unroll
        for (int j = 0; j < 8; j++) { sS[ob + j] = ss[j]; sQ[ob + j] = qq[j]; }
    __syncthreads();
    if (tid < 64) { atomicAdd(&g_sum[tid], sS[tid]); atomicAdd(&g_sq[tid], sQ[tid]); }
    finalize_block(64, 1.0f / 524288.0f, 1, NB * M1, tid, 256);
}

// ---- convT (R6 inner loop, WCH=64) ----
template <int CIN, int COUT, int MM, int DO_MAX>
__global__ __launch_bounds__(256) void convT(const float* __restrict__ in,
                                             const float* __restrict__ wtg,
                                             float* __restrict__ out,
                                             int normStart, int slotIn, int slotOut,
                                             float invN, int outC, int chOff) {
    constexpr int WCH = 64;
    extern __shared__ float sm[];
    float* s_in = sm;
    float* sW = s_in + CIN * 64;
    float* sS = sW + CIN * WCH;
    float* sQ = sS + COUT;
    float* sNm = sQ + COUT;
    float* sRs = sNm + CIN;
    int bm = blockIdx.x, b = bm / MM, m = bm - b * MM;
    int tid = threadIdx.x, lane = tid & 31, wp = tid >> 5;
    size_t MK = (size_t)MM * 64;
    for (int c = tid; c < CIN; c += 256) {
        float mn = 0.0f, rs = 0.0f;
        if (c >= normStart) { mn = g_meanL[slotIn][c - normStart]; rs = g_rstdL[slotIn][c - normStart]; }
        sNm[c] = mn; sRs[c] = rs;
    }
    for (int c = tid; c < COUT; c += 256) { sS[c] = 0.0f; sQ[c] = 0.0f; }
    __syncthreads();
    const float* inb = in + (size_t)b * CIN * MK + (size_t)m * 64;
    for (int i = tid; i < CIN * 64; i += 256) {
        int c = i >> 6;
        float v = inb[(size_t)c * MK + (i & 63)];
        if (c >= normStart) v = fmaxf((v - sNm[c]) * sRs[c], 0.0f);
        s_in[i] = v;
    }
    float* outb = out + (size_t)b * COUT * MK + (size_t)m * 64;
    const float2* xrow = (const float2*)s_in + lane;
    #pragma unroll
    for (int ch0 = 0; ch0 < COUT; ch0 += WCH) {
        __syncthreads();
        for (int i = tid; i < CIN * WCH; i += 256) {
            int c = i >> 6, o = i & 63;
            sW[i] = wtg[(size_t)c * COUT + ch0 + o];
        }
        __syncthreads();
        int ob = wp * 8;
        ull acc[4][2];
        #pragma unroll
        for (int j = 0; j < 4; j++) { acc[j][0] = 0ull; acc[j][1] = 0ull; }
        #pragma unroll 8
        for (int c = 0; c < CIN; c++) {
            float2 xv = xrow[c * 32];
            ull d0, d1;
            PACKF2(d0, xv.x, xv.x); PACKF2(d1, xv.y, xv.y);
            const ull* wr = (const ull*)(sW + (c << 6) + ob);
            ull W0 = wr[0], W1 = wr[1], W2 = wr[2], W3 = wr[3];
            FFMA2(acc[0][0], W0, d0); FFMA2(acc[0][1], W0, d1);
            FFMA2(acc[1][0], W1, d0); FFMA2(acc[1][1], W1, d1);
            FFMA2(acc[2][0], W2, d0); FFMA2(acc[2][1], W2, d1);
            FFMA2(acc[3][0], W3, d0); FFMA2(acc[3][1], W3, d1);
        }
        float a[8][2];
        #pragma unroll
        for (int j = 0; j < 4; j++) {
            UNPACKF2(a[2 * j][0], a[2 * j + 1][0], acc[j][0]);
            UNPACKF2(a[2 * j][1], a[2 * j + 1][1], acc[j][1]);
        }
        int gob = ch0 + ob;
        float ss[8], qq[8], mmx[8];
        #pragma unroll
        for (int j = 0; j < 8; j++) {
            if (!DO_MAX)
                *(float2*)(outb + (size_t)(gob + j) * MK + 2 * lane) = make_float2(a[j][0], a[j][1]);
            ss[j] = a[j][0] + a[j][1];
            qq[j] = a[j][0] * a[j][0] + a[j][1] * a[j][1];
            mmx[j] = fmaxf(a[j][0], a[j][1]);
        }
        #pragma unroll
        for (int o = 16; o; o >>= 1)
            #pragma unroll
            for (int j = 0; j < 8; j++) {
                ss[j] += __shfl_down_sync(0xffffffffu, ss[j], o);
                qq[j] += __shfl_down_sync(0xffffffffu, qq[j], o);
                if (DO_MAX) mmx[j] = fmaxf(mmx[j], __shfl_down_sync(0xffffffffu, mmx[j], o));
            }
        if (lane == 0)
            #pragma unroll
            for (int j = 0; j < 8; j++) {
                sS[gob + j] = ss[j]; sQ[gob + j] = qq[j];
                if (DO_MAX)
                    out[((size_t)b * outC + chOff + gob + j) * MM + m] = mmx[j];
            }
    }
    __syncthreads();
    for (int c = tid; c < COUT; c += 256) { atomicAdd(&g_sum[c], sS[c]); atomicAdd(&g_sq[c], sQ[c]); }
    finalize_block(COUT, invN, slotOut, NB * MM, tid, 256);
}

__global__ __launch_bounds__(128) void bx2_k() {
    int bm = blockIdx.x, b = bm >> 5, m = bm & 31, tid = threadIdx.x;
    __shared__ int sn[64]; __shared__ float sc2[3];
    if (tid < 64) sn[tid] = g_n2[bm * 64 + tid];
    if (tid < 3) sc2[tid] = g_c2[((size_t)b * M2 + m) * 3 + tid];
    __syncthreads();
    for (int i = tid; i < 131 * 64; i += 128) {
        int c = i >> 6, k = i & 63, n = sn[k];
        float v;
        if (c < 3) v = g_c1[((size_t)b * M1 + n) * 3 + c] - sc2[c];
        else {
            float z = g_f1[((size_t)b * 128 + (c - 3)) * M1 + n];
            v = fmaxf((z - g_meanL[2][c - 3]) * g_rstdL[2][c - 3], 0.0f);
        }
        g_bufB[(((size_t)b * 131 + c) * M2 + m) * 64 + k] = v;
    }
}

__global__ __launch_bounds__(256) void conv1_k(const float* __restrict__ in,
                                               const float* __restrict__ wt,
                                               float* __restrict__ out,
                                               int Cin, int Cout,
                                               int normStart, int slotIn,
                                               int slotOut, float invN) {
    extern __shared__ float s_in[];
    int nOc = Cout >> 7;
    int b = blockIdx.x / nOc, oc = blockIdx.x - b * nOc;
    int tid = threadIdx.x, lane = tid & 31, wp = tid >> 5;
    const float* inb = in + (size_t)b * Cin * 32;
    for (int i = tid; i < Cin * 32; i += 256) {
        int c = i >> 5;
        float v = inb[i];
        if (c >= normStart) v = fmaxf((v - g_meanL[slotIn][c - normStart]) * g_rstdL[slotIn][c - normStart], 0.0f);
        s_in[i] = v;
    }
    __syncthreads();
    float* outb = out + (size_t)b * Cout * 32;
    for (int ob = oc * 128 + wp * 8; ob < oc * 128 + 128; ob += 64) {
        float a[8];
        #pragma unroll
        for (int j = 0; j < 8; j++) a[j] = 0.0f;
        const float4* wp4 = (const float4*)(wt + ob);
        int cstep = Cout >> 2;
        #pragma unroll 4
        for (int c = 0; c < Cin; c++) {
            float x = s_in[(c << 5) + lane];
            float4 w0 = wp4[c * cstep];
            float4 w1 = wp4[c * cstep + 1];
            a[0] += w0.x * x; a[1] += w0.y * x; a[2] += w0.z * x; a[3] += w0.w * x;
            a[4] += w1.x * x; a[5] += w1.y * x; a[6] += w1.z * x; a[7] += w1.w * x;
        }
        float qq[8];
        #pragma unroll
        for (int j = 0; j < 8; j++) {
            outb[(ob + j) * 32 + lane] = a[j];
            qq[j] = a[j] * a[j];
        }
        #pragma unroll
        for (int o = 16; o; o >>= 1)
            #pragma unroll
            for (int j = 0; j < 8; j++) {
                a[j] += __shfl_down_sync(0xffffffffu, a[j], o);
                qq[j] += __shfl_down_sync(0xffffffffu, qq[j], o);
            }
        if (lane == 0)
            #pragma unroll
            for (int j = 0; j < 8; j++) {
                atomicAdd(&g_sum[ob + j], a[j]); atomicAdd(&g_sq[ob + j], qq[j]);
            }
    }
    finalize_block(Cout, invN, slotOut, NB * nOc, tid, 256);
}

__global__ void cc2_k() {
    int b = blockIdx.x, t = threadIdx.x;
    if (t < 96) {
        int c = t / 32, m = t % 32;
        g_x3[((size_t)(b * 259 + c)) * 32 + m] = g_c2[((size_t)b * 32 + m) * 3 + c];
    }
}

__global__ void mp3_k(const float* __restrict__ in, const float* __restrict__ oneh) {
    int b = blockIdx.x, o = threadIdx.x;
    const float* p = in + ((size_t)b * 512 + o) * 32;
    float v = p[0];
    #pragma unroll
    for (int m = 1; m < 32; m++) v = fmaxf(v, p[m]);
    g_xc[o * 64 + b] = fmaxf((v - g_meanL[8][o]) * g_rstdL[8][o], 0.0f);
    if (o < 3) g_xc[(512 + o) * 64 + b] = oneh[b * 3 + o];
}

__global__ void fc_k(const float* __restrict__ x, const float* __restrict__ w,
                     float* __restrict__ out, int Cin) {
    __shared__ float sm2[2], sqv[2];
    int o = blockIdx.x, b = threadIdx.x;
    const float* wr = w + (size_t)o * Cin;
    float z = 0.0f;
    for (int c = 0; c < Cin; c++) z += x[c * 64 + b] * wr[c];
    float s = z, q = z * z;
    #pragma unroll
    for (int off = 16; off; off >>= 1) {
        s += __shfl_down_sync(0xffffffffu, s, off);
        q += __shfl_down_sync(0xffffffffu, q, off);
    }
    if ((b & 31) == 0) { sm2[b >> 5] = s; sqv[b >> 5] = q; }
    __syncthreads();
    float mn = (sm2[0] + sm2[1]) * (1.0f / 64.0f);
    float vq = (sqv[0] + sqv[1]) * (1.0f / 64.0f);
    out[o * 64 + b] = fmaxf((z - mn) * rsqrtf(vq - mn * mn + 1e-5f), 0.0f);
}

__global__ void fco_k(const float* __restrict__ x, const float* __restrict__ w,
                      const float* __restrict__ bias, float* __restrict__ out) {
    int o = blockIdx.x, b = threadIdx.x;
    const float* wr = w + (size_t)o * 256;
    float z = bias[o];
    for (int c = 0; c < 256; c++) z += x[c * 64 + b] * wr[c];
    out[b * 59 + o] = z;
}

extern "C" void kernel_launch(void* const* d_in, const int* in_sizes, int n_in,
                              void* d_out, int out_size) {
    const float* coords = (const float*)d_in[0];
    const float* oneh   = (const float*)d_in[1];

    float *bufA, *bufB, *wt, *f1, *x3, *z3a, *z3b, *xc, *fa1, *fa2;
    cudaGetSymbolAddress((void**)&bufA, g_bufA);
    cudaGetSymbolAddress((void**)&bufB, g_bufB);
    cudaGetSymbolAddress((void**)&wt, g_wt);
    cudaGetSymbolAddress((void**)&f1, g_f1);
    cudaGetSymbolAddress((void**)&x3, g_x3);
    cudaGetSymbolAddress((void**)&z3a, g_z3a);
    cudaGetSymbolAddress((void**)&z3b, g_z3b);
    cudaGetSymbolAddress((void**)&xc, g_xc);
    cudaGetSymbolAddress((void**)&fa1, g_fa1);
    cudaGetSymbolAddress((void**)&fa2, g_fa2);

    const int sm_64    = (64 * 64 + 64 * 64 + 2 * 128 + 2 * 64) * 4;
    const int sm_131   = (131 * 64 + 131 * 64 + 2 * 128 + 2 * 131) * 4;
    const int sm_128a  = (128 * 64 + 128 * 64 + 2 * 128 + 2 * 128) * 4;
    const int sm_128b  = (128 * 64 + 128 * 64 + 2 * 256 + 2 * 128) * 4;
    cudaFuncSetAttribute(convT<64, 128, M1, 1>, cudaFuncAttributeMaxDynamicSharedMemorySize, sm_64);
    cudaFuncSetAttribute(convT<131, 128, M2, 0>, cudaFuncAttributeMaxDynamicSharedMemorySize, sm_131);
    cudaFuncSetAttribute(convT<128, 128, M2, 0>, cudaFuncAttributeMaxDynamicSharedMemorySize, sm_128a);
    cudaFuncSetAttribute(convT<128, 256, M2, 1>, cudaFuncAttributeMaxDynamicSharedMemorySize, sm_128b);

    // 0: fused fps + ball-query stage 1
    fpsbq1_k<<<NB, 1024>>>(coords);
    // 1: weight transposes
    tw_all<<<256, 256>>>((const float*)d_in[2], (const float*)d_in[3], (const float*)d_in[4],
                         (const float*)d_in[5], (const float*)d_in[6], (const float*)d_in[7],
                         (const float*)d_in[8], (const float*)d_in[9], (const float*)d_in[10]);
    // 2: gather + 3->64 conv (slot0)
    convA_k<<<NB * M1, 256>>>(coords, (const float*)d_in[2]);
    // 3: 64->64 conv (slot1) [ncu target; R5 variant, stride 68]
    convB_k<<<NB * M1, 256>>>((const float*)d_in[3]);
    // 4: 64->128 conv + fused maxpool -> f1 (slot2)
    convT<64, 128, M1, 1><<<NB * M1, 256, sm_64>>>(bufB, wt + 4288, f1, 0, 1, 2,
                                                   1.0f / 524288.0f, 128, 0);
    // 5-6: stage-2 sampling + input build
    fpsbq2_k<<<NB, 128>>>();
    bx2_k<<<NB * M2, 128>>>();
    // 7-9: stage-2 MLP
    convT<131, 128, M2, 0><<<NB * M2, 256, sm_131>>>(bufB, wt + 12480, bufA, 131, 0, 3,
                                                     1.0f / 131072.0f, 0, 0);
    convT<128, 128, M2, 0><<<NB * M2, 256, sm_128a>>>(bufA, wt + 29248, bufB, 0, 3, 4,
                                                      1.0f / 131072.0f, 0, 0);
    convT<128, 256, M2, 1><<<NB * M2, 256, sm_128b>>>(bufB, wt + 45632, x3, 0, 4, 5,
                                                      1.0f / 131072.0f, 259, 3);
    // 10: centers into x3 channels 0-2
    cc2_k<<<NB, 96>>>();
    // 11-13: stage-3 convs
    conv1_k<<<NB * 2, 256, 259 * 32 * 4>>>(x3, wt + 78400, z3b, 259, 256, 3, 5, 6, 1.0f / 2048.0f);
    conv1_k<<<NB * 2, 256, 256 * 32 * 4>>>(z3b, wt + 144704, z3a, 256, 256, 0, 6, 7, 1.0f / 2048.0f);
    conv1_k<<<NB * 4, 256, 256 * 32 * 4>>>(z3a, wt + 210240, bufA, 256, 512, 0, 7, 8, 1.0f / 2048.0f);
    // 14: global max + onehot
    mp3_k<<<NB, 512>>>(bufA, oneh);
    // 15-17: FC head
    fc_k<<<512, 64>>>(xc, (const float*)d_in[11], fa1, 515);
    fc_k<<<256, 64>>>(fa1, (const float*)d_in[12], fa2, 512);
    fco_k<<<59, 64>>>(fa2, (const float*)d_in[13], (const float*)d_in[14], (float*)d_out);
}